// round 2
// baseline (speedup 1.0000x reference)
#include <cuda_runtime.h>
#include <math.h>

#define BB 32
#define TT 512
#define EE 512
#define HH 512
#define CC 32
#define MM (BB*TT)        /* 16384 token positions, m' = t*32 + b */
#define G4 (4*HH)         /* 2048 gate columns per direction */
#define NBLK 128          /* persistent LSTM grid: 64 blocks per direction */

/* ------------------------ scratch (static device memory) ------------------- */
__device__ float g_emb[(size_t)MM*EE];      /* layer0 input  [m'][512]   */
__device__ float g_xw0[(size_t)MM*G4];      /* xw forward    [m'][2048]  */
__device__ float g_xw1[(size_t)MM*G4];      /* xw backward   [m'][2048]  */
__device__ float g_l0out[(size_t)MM*2*HH];  /* layer0 output [m'][1024]  */
__device__ float g_l1out[(size_t)MM*2*HH];  /* layer1 output [m'][1024]  */
__device__ float g_hbuf[2*2*BB*HH];         /* [dir][parity][b][h]       */
__device__ unsigned g_bar_cnt[2] = {0, 0};
__device__ unsigned g_bar_gen[2] = {0, 0};

/* --------------------- per-direction grid barrier (64 blocks) -------------- */
__device__ __forceinline__ void dir_sync(int dir) {
    __syncthreads();
    if (threadIdx.x == 0) {
        unsigned gen = *(volatile unsigned*)&g_bar_gen[dir];
        __threadfence();
        if (atomicAdd(&g_bar_cnt[dir], 1u) == (NBLK/2) - 1) {
            atomicExch(&g_bar_cnt[dir], 0u);
            __threadfence();
            atomicAdd(&g_bar_gen[dir], 1u);
        } else {
            while (*(volatile unsigned*)&g_bar_gen[dir] == gen) { }
        }
        __threadfence();
    }
    __syncthreads();
}

/* ------------------------------ embedding ---------------------------------- */
__global__ __launch_bounds__(256) void embed_kernel(const int* __restrict__ x,
                                                    const float* __restrict__ emb) {
    int gid  = blockIdx.x * blockDim.x + threadIdx.x;
    int mp   = gid >> 5;
    int lane = gid & 31;
    int b  = mp & 31;
    int tt = mp >> 5;
    int v  = x[b*TT + tt];
    const float4* src = (const float4*)(emb + (size_t)v*EE);
    float4* dst = (float4*)(g_emb + (size_t)mp*EE);
#pragma unroll
    for (int r = 0; r < EE/128; r++)
        dst[r*32 + lane] = src[r*32 + lane];
}

/* --------------------- input GEMM: xw = X @ W^T + bih + bhh ---------------- */
#define BMg 128
#define BNg 64
#define BKg 16

__global__ __launch_bounds__(256) void gemm_xw_kernel(
        int layer,
        const float* __restrict__ Wf, const float* __restrict__ bif, const float* __restrict__ bhf,
        const float* __restrict__ Wb, const float* __restrict__ bib, const float* __restrict__ bhb) {
    const int K = layer ? 2*HH : EE;
    const float* A = layer ? g_l0out : g_emb;
    int dir = blockIdx.z;
    const float* W  = dir ? Wb  : Wf;
    const float* bi = dir ? bib : bif;
    const float* bh = dir ? bhb : bhf;
    float* out = dir ? g_xw1 : g_xw0;

    __shared__ float As[BKg][BMg + 8];
    __shared__ float Bs[BKg][BNg + 8];

    int t  = threadIdx.x;
    int m0 = blockIdx.y * BMg;
    int n0 = blockIdx.x * BNg;
    int tx = t & 15, ty = t >> 4;

    float acc[8][4];
#pragma unroll
    for (int i = 0; i < 8; i++)
#pragma unroll
        for (int j = 0; j < 4; j++) acc[i][j] = 0.f;

    float4 bias;
    {
        int n = n0 + tx*4;
        bias.x = bi[n+0] + bh[n+0];
        bias.y = bi[n+1] + bh[n+1];
        bias.z = bi[n+2] + bh[n+2];
        bias.w = bi[n+3] + bh[n+3];
    }

    int ar = t >> 1, aq = (t & 1) * 8;
    int bn = t & 63, bq = (t >> 6) * 4;

    for (int k0 = 0; k0 < K; k0 += BKg) {
        float4 a0 = *(const float4*)(A + (size_t)(m0+ar)*K + k0 + aq);
        float4 a1 = *(const float4*)(A + (size_t)(m0+ar)*K + k0 + aq + 4);
        float4 bv = *(const float4*)(W + (size_t)(n0+bn)*K + k0 + bq);
        __syncthreads();
        As[aq+0][ar] = a0.x; As[aq+1][ar] = a0.y; As[aq+2][ar] = a0.z; As[aq+3][ar] = a0.w;
        As[aq+4][ar] = a1.x; As[aq+5][ar] = a1.y; As[aq+6][ar] = a1.z; As[aq+7][ar] = a1.w;
        Bs[bq+0][bn] = bv.x; Bs[bq+1][bn] = bv.y; Bs[bq+2][bn] = bv.z; Bs[bq+3][bn] = bv.w;
        __syncthreads();
#pragma unroll
        for (int k = 0; k < BKg; k++) {
            float4 ra0 = *(const float4*)&As[k][ty*8];
            float4 ra1 = *(const float4*)&As[k][ty*8 + 4];
            float4 rb  = *(const float4*)&Bs[k][tx*4];
            float av[8]  = {ra0.x, ra0.y, ra0.z, ra0.w, ra1.x, ra1.y, ra1.z, ra1.w};
            float bvv[4] = {rb.x, rb.y, rb.z, rb.w};
#pragma unroll
            for (int i = 0; i < 8; i++)
#pragma unroll
                for (int j = 0; j < 4; j++)
                    acc[i][j] = fmaf(av[i], bvv[j], acc[i][j]);
        }
    }

#pragma unroll
    for (int i = 0; i < 8; i++) {
        float4 o;
        o.x = acc[i][0] + bias.x;
        o.y = acc[i][1] + bias.y;
        o.z = acc[i][2] + bias.z;
        o.w = acc[i][3] + bias.w;
        *(float4*)(out + (size_t)(m0 + ty*8 + i)*G4 + n0 + tx*4) = o;
    }
}

/* ------------------------- persistent recurrent scan ----------------------- */
#define WS_STRIDE 520
#define HS_STRIDE 516
#define XW_STRIDE 36
#define LSTM_SMEM ((32*WS_STRIDE + 32*HS_STRIDE + 32*XW_STRIDE + 8*33) * 4)

__global__ __launch_bounds__(256) void lstm_kernel(int layer,
        const float* __restrict__ WhhF, const float* __restrict__ WhhB) {
    extern __shared__ float sm[];
    float* W_s    = sm;                       /* [32 gate rows][520] */
    float* h_s    = W_s  + 32*WS_STRIDE;      /* [32 batch][516]     */
    float* xw_s   = h_s  + 32*HS_STRIDE;      /* [32 batch][36]      */
    float* hout_s = xw_s + 32*XW_STRIDE;      /* [8 h][33]           */

    int t    = threadIdx.x;
    int lane = t & 31;            /* batch index        */
    int w    = t >> 5;            /* local h index 0..7 */
    int dir  = blockIdx.x >> 6;
    int hb   = (blockIdx.x & 63) << 3;
    const float* Whh = dir ? WhhB : WhhF;
    const float* xw  = dir ? g_xw1 : g_xw0;
    float* out  = layer ? g_l1out : g_l0out;
    float* hbuf = g_hbuf + dir*2*BB*HH;

    /* stage Whh slice: row g*512 + hb + j  ->  W_s[g*8 + j][k] */
    {
        int r  = t >> 3;
        int kq = (t & 7) * 64;
        int g = r >> 3, j = r & 7;
        const float* src = Whh + (size_t)(g*HH + hb + j)*HH + kq;
        float* dst = W_s + r*WS_STRIDE + kq;
#pragma unroll
        for (int i = 0; i < 16; i++)
            *(float4*)(dst + i*4) = *(const float4*)(src + i*4);
    }

    float c = 0.f;

    for (int it = 0; it < TT; it++) {
        int tstep = dir ? (TT - 1 - it) : it;

        /* stage h_{t-1} (32x512) */
        {
            int b  = t >> 3;
            int k0 = (t & 7) * 64;
            float* dst = h_s + b*HS_STRIDE + k0;
            if (it == 0) {
#pragma unroll
                for (int i = 0; i < 16; i++)
                    *(float4*)(dst + i*4) = make_float4(0.f, 0.f, 0.f, 0.f);
            } else {
                const float* src = hbuf + ((it & 1) ? BB*HH : 0) + b*HH + k0;
#pragma unroll
                for (int i = 0; i < 16; i++)
                    *(float4*)(dst + i*4) = __ldcg((const float4*)(src + i*4));
            }
        }
        /* stage xw tile: 32 batch x (4 gates x 8 h) */
        {
            int b = t >> 3, gq = t & 7;
            int g = gq >> 1, half = (gq & 1) * 4;
            float4 v = *(const float4*)(xw + (size_t)(tstep*32 + b)*G4 + g*HH + hb + half);
            *(float4*)(xw_s + b*XW_STRIDE + g*8 + half) = v;
        }
        __syncthreads();

        float a0 = xw_s[lane*XW_STRIDE + 0*8 + w];
        float a1 = xw_s[lane*XW_STRIDE + 1*8 + w];
        float a2 = xw_s[lane*XW_STRIDE + 2*8 + w];
        float a3 = xw_s[lane*XW_STRIDE + 3*8 + w];

        const float4* hp  = (const float4*)(h_s + lane*HS_STRIDE);
        const float4* w0p = (const float4*)(W_s + (0*8 + w)*WS_STRIDE);
        const float4* w1p = (const float4*)(W_s + (1*8 + w)*WS_STRIDE);
        const float4* w2p = (const float4*)(W_s + (2*8 + w)*WS_STRIDE);
        const float4* w3p = (const float4*)(W_s + (3*8 + w)*WS_STRIDE);

#pragma unroll 8
        for (int kk = 0; kk < 128; kk++) {
            float4 hv = hp[kk];
            float4 w0 = w0p[kk], w1 = w1p[kk], w2 = w2p[kk], w3 = w3p[kk];
            a0 = fmaf(hv.x,w0.x, fmaf(hv.y,w0.y, fmaf(hv.z,w0.z, fmaf(hv.w,w0.w, a0))));
            a1 = fmaf(hv.x,w1.x, fmaf(hv.y,w1.y, fmaf(hv.z,w1.z, fmaf(hv.w,w1.w, a1))));
            a2 = fmaf(hv.x,w2.x, fmaf(hv.y,w2.y, fmaf(hv.z,w2.z, fmaf(hv.w,w2.w, a2))));
            a3 = fmaf(hv.x,w3.x, fmaf(hv.y,w3.y, fmaf(hv.z,w3.z, fmaf(hv.w,w3.w, a3))));
        }

        /* torch gate order i, f, g, o */
        float ig = 1.f / (1.f + expf(-a0));
        float fg = 1.f / (1.f + expf(-a1));
        float gg = tanhf(a2);
        float og = 1.f / (1.f + expf(-a3));
        c = fg*c + ig*gg;
        float hv = og * tanhf(c);
        hout_s[w*33 + lane] = hv;
        __syncthreads();

        {
            int b = t >> 3, j = t & 7;
            float v = hout_s[j*33 + b];
            __stcg(hbuf + (((it + 1) & 1) ? BB*HH : 0) + b*HH + hb + j, v);
            out[(size_t)(tstep*32 + b)*(2*HH) + dir*HH + hb + j] = v;
        }
        __threadfence();
        dir_sync(dir);
    }
}

/* --------------------- classifier + log_softmax + transpose ---------------- */
__global__ __launch_bounds__(256) void cls_kernel(const float* __restrict__ truth,
        const int* __restrict__ tf, const float* __restrict__ Wc,
        const float* __restrict__ bc, float* __restrict__ out) {
    __shared__ float Fs[64*68];
    __shared__ float Ws[32*68];
    __shared__ float Ls[64*33];
    __shared__ float lse[64];

    int t  = threadIdx.x;
    int p0 = blockIdx.x * 64;
    int p  = t & 63, cg = t >> 6;

    float acc[8];
#pragma unroll
    for (int j = 0; j < 8; j++) acc[j] = 0.f;

    for (int kc = 0; kc < 2*HH; kc += 64) {
        __syncthreads();
#pragma unroll
        for (int pass = 0; pass < 4; pass++) {
            int pp = pass*16 + (t >> 4);
            int kq = (t & 15) * 4;
            *(float4*)(Fs + pp*68 + kq) =
                *(const float4*)(g_l1out + (size_t)(p0 + pp)*(2*HH) + kc + kq);
        }
        {
            int cc = t >> 3, j0 = (t & 7) * 8;
            const float* src = Wc + (size_t)cc*(2*HH + 1) + 1 + kc + j0;
            float* dst = Ws + cc*68 + j0;
#pragma unroll
            for (int i = 0; i < 8; i++) dst[i] = src[i];
        }
        __syncthreads();
#pragma unroll
        for (int kk = 0; kk < 16; kk++) {
            float4 f = *(const float4*)(Fs + p*68 + kk*4);
#pragma unroll
            for (int j = 0; j < 8; j++) {
                float4 wv = *(const float4*)(Ws + (cg*8 + j)*68 + kk*4);
                acc[j] = fmaf(f.x,wv.x, fmaf(f.y,wv.y, fmaf(f.z,wv.z, fmaf(f.w,wv.w, acc[j]))));
            }
        }
    }

    int mp = p0 + p;
    int b  = mp & 31;
    int tt = mp >> 5;
    float past = 0.f;
    if (tt > 0 && tf[0] != 0) past = truth[b*TT + tt - 1];
#pragma unroll
    for (int j = 0; j < 8; j++) {
        int cc = cg*8 + j;
        acc[j] += bc[cc] + past * Wc[(size_t)cc*(2*HH + 1)];
        Ls[p*33 + cc] = acc[j];
    }
    __syncthreads();
    if (t < 64) {
        float m = -1e30f;
#pragma unroll
        for (int cc = 0; cc < CC; cc++) m = fmaxf(m, Ls[t*33 + cc]);
        float s = 0.f;
#pragma unroll
        for (int cc = 0; cc < CC; cc++) s += expf(Ls[t*33 + cc] - m);
        lse[t] = m + logf(s);
    }
    __syncthreads();
    {
        float l = lse[p];
#pragma unroll
        for (int j = 0; j < 8; j++) {
            int cc = cg*8 + j;
            out[(size_t)b*CC*TT + (size_t)cc*TT + tt] = Ls[p*33 + cc] - l;
        }
    }
}

/* ------------------------------- launch ------------------------------------ */
extern "C" void kernel_launch(void* const* d_in, const int* in_sizes, int n_in,
                              void* d_out, int out_size) {
    (void)in_sizes; (void)n_in; (void)out_size;
    const int*   x     = (const int*)  d_in[0];
    const float* truth = (const float*)d_in[1];
    const int*   tf    = (const int*)  d_in[2];
    const float* emb   = (const float*)d_in[3];
    const float* Wih0f = (const float*)d_in[4];
    const float* Whh0f = (const float*)d_in[5];
    const float* bih0f = (const float*)d_in[6];
    const float* bhh0f = (const float*)d_in[7];
    const float* Wih0b = (const float*)d_in[8];
    const float* Whh0b = (const float*)d_in[9];
    const float* bih0b = (const float*)d_in[10];
    const float* bhh0b = (const float*)d_in[11];
    const float* Wih1f = (const float*)d_in[12];
    const float* Whh1f = (const float*)d_in[13];
    const float* bih1f = (const float*)d_in[14];
    const float* bhh1f = (const float*)d_in[15];
    const float* Wih1b = (const float*)d_in[16];
    const float* Whh1b = (const float*)d_in[17];
    const float* bih1b = (const float*)d_in[18];
    const float* bhh1b = (const float*)d_in[19];
    const float* Wc    = (const float*)d_in[20];
    const float* bc    = (const float*)d_in[21];
    float* out = (float*)d_out;

    cudaFuncSetAttribute(lstm_kernel,
                         cudaFuncAttributeMaxDynamicSharedMemorySize, LSTM_SMEM);

    embed_kernel<<<MM/8, 256>>>(x, emb);

    dim3 g0(G4/BNg, MM/BMg, 2);
    gemm_xw_kernel<<<g0, 256>>>(0, Wih0f, bih0f, bhh0f, Wih0b, bih0b, bhh0b);
    lstm_kernel<<<NBLK, 256, LSTM_SMEM>>>(0, Whh0f, Whh0b);

    gemm_xw_kernel<<<g0, 256>>>(1, Wih1f, bih1f, bhh1f, Wih1b, bih1b, bhh1b);
    lstm_kernel<<<NBLK, 256, LSTM_SMEM>>>(1, Whh1f, Whh1b);

    cls_kernel<<<MM/64, 256>>>(truth, tf, Wc, bc, out);
}

// round 4
// speedup vs baseline: 1.1435x; 1.1435x over previous
#include <cuda_runtime.h>
#include <cuda_bf16.h>
#include <math.h>
#include <stdint.h>

#define BB 32
#define TT 512
#define EE 512
#define HH 512
#define CC 32
#define MM (BB*TT)        /* 16384 token positions, m' = t*32 + b */
#define G4 (4*HH)         /* 2048 gate columns per direction */
#define NBLK 128          /* persistent LSTM grid: 64 blocks per direction */

/* ------------------------ scratch (static device memory) ------------------- */
__device__ __nv_bfloat16 g_embh[(size_t)MM*EE];    /* layer0 GEMM input (bf16) */
__device__ __nv_bfloat16 g_l0h[(size_t)MM*2*HH];   /* layer0 output     (bf16) */
__device__ __nv_bfloat16 g_Wbf[2*(size_t)G4*EE + 2*(size_t)G4*2*HH]; /* Wih bf16 */
__device__ float g_xw0[(size_t)MM*G4];             /* xw forward  [m'][2048]   */
__device__ float g_xw1[(size_t)MM*G4];             /* xw backward [m'][2048]   */
__device__ float g_l1out[(size_t)MM*2*HH];         /* layer1 output [m'][1024] */
__device__ float g_hbuf[2*2*BB*HH];                /* [dir][parity][b][h]      */
__device__ unsigned g_bar_cnt[2] = {0, 0};
__device__ unsigned g_bar_gen[2] = {0, 0};

/* Wbf offsets */
#define WOFF_L0F ((size_t)0)
#define WOFF_L0B ((size_t)G4*EE)
#define WOFF_L1F ((size_t)2*G4*EE)
#define WOFF_L1B ((size_t)2*G4*EE + (size_t)G4*2*HH)

/* --------------------- per-direction grid barrier (64 blocks) -------------- */
__device__ __forceinline__ void dir_sync(int dir) {
    __syncthreads();
    if (threadIdx.x == 0) {
        unsigned gen = *(volatile unsigned*)&g_bar_gen[dir];
        __threadfence();
        if (atomicAdd(&g_bar_cnt[dir], 1u) == (NBLK/2) - 1) {
            atomicExch(&g_bar_cnt[dir], 0u);
            __threadfence();
            atomicAdd(&g_bar_gen[dir], 1u);
        } else {
            while (*(volatile unsigned*)&g_bar_gen[dir] == gen) { }
        }
        __threadfence();
    }
    __syncthreads();
}

/* ------------------------------ embedding (f32 -> bf16) -------------------- */
__global__ __launch_bounds__(256) void embed_kernel(const int* __restrict__ x,
                                                    const float* __restrict__ emb) {
    int gid  = blockIdx.x * blockDim.x + threadIdx.x;
    int mp   = gid >> 5;
    int lane = gid & 31;
    int b  = mp & 31;
    int tt = mp >> 5;
    int v  = x[b*TT + tt];
    const float4* src = (const float4*)(emb + (size_t)v*EE);
    __nv_bfloat162* dst = (__nv_bfloat162*)(g_embh + (size_t)mp*EE);
#pragma unroll
    for (int r = 0; r < EE/128; r++) {
        float4 f = src[r*32 + lane];
        dst[(r*32 + lane)*2 + 0] = __floats2bfloat162_rn(f.x, f.y);
        dst[(r*32 + lane)*2 + 1] = __floats2bfloat162_rn(f.z, f.w);
    }
}

/* --------------------------- f32 -> bf16 convert --------------------------- */
__global__ __launch_bounds__(256) void f2bf_kernel(const float* __restrict__ src,
                                                   __nv_bfloat16* __restrict__ dst,
                                                   int n4) {
    int i = blockIdx.x * blockDim.x + threadIdx.x;
    if (i < n4) {
        float4 f = *(const float4*)(src + (size_t)i*4);
        __nv_bfloat162* d = (__nv_bfloat162*)(dst + (size_t)i*4);
        d[0] = __floats2bfloat162_rn(f.x, f.y);
        d[1] = __floats2bfloat162_rn(f.z, f.w);
    }
}

/* ---------------- bf16 tensor-core GEMM: xw = A @ W^T + bih + bhh ----------
 * A: [M][K] bf16 row-major, W: [2048][K] bf16 row-major (acts as B col-major)
 * Block tile 128x128x32, 8 warps (4 in M x 2 in N), warp tile 32x64.        */
#define GBM 128
#define GBN 128
#define GBK 32
#define LDS_W 40   /* bf16 per smem row (80B => stride 20 banks, conflict-free) */

__device__ __forceinline__ void ldmatrix_x4(uint32_t& d0, uint32_t& d1,
                                            uint32_t& d2, uint32_t& d3,
                                            uint32_t addr) {
    asm volatile("ldmatrix.sync.aligned.m8n8.x4.shared.b16 {%0,%1,%2,%3}, [%4];"
                 : "=r"(d0), "=r"(d1), "=r"(d2), "=r"(d3) : "r"(addr));
}
__device__ __forceinline__ void mma_bf16(float* c, const uint32_t* a, const uint32_t* b) {
    asm volatile("mma.sync.aligned.m16n8k16.row.col.f32.bf16.bf16.f32 "
                 "{%0,%1,%2,%3}, {%4,%5,%6,%7}, {%8,%9}, {%0,%1,%2,%3};"
                 : "+f"(c[0]), "+f"(c[1]), "+f"(c[2]), "+f"(c[3])
                 : "r"(a[0]), "r"(a[1]), "r"(a[2]), "r"(a[3]), "r"(b[0]), "r"(b[1]));
}

__global__ __launch_bounds__(256) void gemm_bf16_kernel(
        int layer,
        const float* __restrict__ bif, const float* __restrict__ bhf,
        const float* __restrict__ bib, const float* __restrict__ bhb) {
    const int K = layer ? 2*HH : EE;
    const __nv_bfloat16* A = layer ? g_l0h : g_embh;
    int dir = blockIdx.z;
    const __nv_bfloat16* W = g_Wbf + (layer ? (dir ? WOFF_L1B : WOFF_L1F)
                                            : (dir ? WOFF_L0B : WOFF_L0F));
    const float* bi = dir ? bib : bif;
    const float* bh = dir ? bhb : bhf;
    float* out = dir ? g_xw1 : g_xw0;

    __shared__ __nv_bfloat16 As[GBM*LDS_W];
    __shared__ __nv_bfloat16 Bs[GBN*LDS_W];

    int t = threadIdx.x;
    int m0 = blockIdx.y * GBM;
    int n0 = blockIdx.x * GBN;
    int warp = t >> 5, lane = t & 31;
    int wm0 = (warp & 3) * 32;
    int wn0 = (warp >> 2) * 64;

    /* global staging indices: 64 rows x 4 16B-chunks per 256 threads */
    int lr = t >> 2;
    int lc = (t & 3) * 8;
    const __nv_bfloat16* Ag = A + (size_t)(m0 + lr) * K + lc;
    const __nv_bfloat16* Wg = W + (size_t)(n0 + lr) * K + lc;

    float c[2][8][4];
#pragma unroll
    for (int i = 0; i < 2; i++)
#pragma unroll
        for (int j = 0; j < 8; j++)
#pragma unroll
            for (int q = 0; q < 4; q++) c[i][j][q] = 0.f;

    /* ldmatrix per-thread source rows/cols */
    int arow = (lane & 7) + ((lane >> 3) & 1) * 8;   /* + mt*16 */
    int acol = (lane >> 4) * 8;                       /* + ks    */
    int brow = ((lane >> 4) * 8) + (lane & 7);        /* + p*16  */
    int bcol = ((lane >> 3) & 1) * 8;                 /* + ks    */

    uint32_t as_base = (uint32_t)__cvta_generic_to_shared(As);
    uint32_t bs_base = (uint32_t)__cvta_generic_to_shared(Bs);

    const int nk = K / GBK;
    uint4 pa0 = *(const uint4*)(Ag);
    uint4 pa1 = *(const uint4*)(Ag + (size_t)64*K);
    uint4 pb0 = *(const uint4*)(Wg);
    uint4 pb1 = *(const uint4*)(Wg + (size_t)64*K);

    for (int kt = 0; kt < nk; kt++) {
        *(uint4*)(As + lr*LDS_W + lc)        = pa0;
        *(uint4*)(As + (lr+64)*LDS_W + lc)   = pa1;
        *(uint4*)(Bs + lr*LDS_W + lc)        = pb0;
        *(uint4*)(Bs + (lr+64)*LDS_W + lc)   = pb1;
        __syncthreads();
        if (kt + 1 < nk) {
            int ko = (kt + 1) * GBK;
            pa0 = *(const uint4*)(Ag + ko);
            pa1 = *(const uint4*)(Ag + (size_t)64*K + ko);
            pb0 = *(const uint4*)(Wg + ko);
            pb1 = *(const uint4*)(Wg + (size_t)64*K + ko);
        }
#pragma unroll
        for (int ks = 0; ks < GBK; ks += 16) {
            uint32_t a[2][4];
            uint32_t b[8][2];
#pragma unroll
            for (int mt = 0; mt < 2; mt++) {
                uint32_t addr = as_base +
                    (uint32_t)(((wm0 + mt*16 + arow)*LDS_W + ks + acol) * 2);
                ldmatrix_x4(a[mt][0], a[mt][1], a[mt][2], a[mt][3], addr);
            }
#pragma unroll
            for (int p = 0; p < 4; p++) {
                uint32_t addr = bs_base +
                    (uint32_t)(((wn0 + p*16 + brow)*LDS_W + ks + bcol) * 2);
                ldmatrix_x4(b[2*p][0], b[2*p][1], b[2*p+1][0], b[2*p+1][1], addr);
            }
#pragma unroll
            for (int mt = 0; mt < 2; mt++)
#pragma unroll
                for (int nt = 0; nt < 8; nt++)
                    mma_bf16(c[mt][nt], a[mt], b[nt]);
        }
        __syncthreads();
    }

    /* epilogue: C fragment -> gmem with bias */
    int g  = lane >> 2;
    int cp = (lane & 3) * 2;
#pragma unroll
    for (int nt = 0; nt < 8; nt++) {
        int n = n0 + wn0 + nt*8 + cp;
        float b0 = bi[n]   + bh[n];
        float b1 = bi[n+1] + bh[n+1];
#pragma unroll
        for (int mt = 0; mt < 2; mt++) {
            int r = m0 + wm0 + mt*16 + g;
            float2 v0 = make_float2(c[mt][nt][0] + b0, c[mt][nt][1] + b1);
            float2 v1 = make_float2(c[mt][nt][2] + b0, c[mt][nt][3] + b1);
            *(float2*)(out + (size_t)r*G4 + n)       = v0;
            *(float2*)(out + (size_t)(r+8)*G4 + n)   = v1;
        }
    }
}

/* ------------------------- persistent recurrent scan ----------------------- */
#define WS_STRIDE 520
#define HS_STRIDE 516
#define XW_STRIDE 36
#define LSTM_SMEM ((32*WS_STRIDE + 32*HS_STRIDE + 32*XW_STRIDE + 8*33) * 4)

__global__ __launch_bounds__(256) void lstm_kernel(int layer,
        const float* __restrict__ WhhF, const float* __restrict__ WhhB) {
    extern __shared__ float sm[];
    float* W_s    = sm;                       /* [32 gate rows][520] */
    float* h_s    = W_s  + 32*WS_STRIDE;      /* [32 batch][516]     */
    float* xw_s   = h_s  + 32*HS_STRIDE;      /* [32 batch][36]      */
    float* hout_s = xw_s + 32*XW_STRIDE;      /* [8 h][33]           */

    int t    = threadIdx.x;
    int lane = t & 31;            /* batch index        */
    int w    = t >> 5;            /* local h index 0..7 */
    int dir  = blockIdx.x >> 6;
    int hb   = (blockIdx.x & 63) << 3;
    const float* Whh = dir ? WhhB : WhhF;
    const float* xw  = dir ? g_xw1 : g_xw0;
    float* hbuf = g_hbuf + dir*2*BB*HH;

    /* stage Whh slice: row g*512 + hb + j  ->  W_s[g*8 + j][k] */
    {
        int r  = t >> 3;
        int kq = (t & 7) * 64;
        int gg = r >> 3, j = r & 7;
        const float* src = Whh + (size_t)(gg*HH + hb + j)*HH + kq;
        float* dst = W_s + r*WS_STRIDE + kq;
#pragma unroll
        for (int i = 0; i < 16; i++)
            *(float4*)(dst + i*4) = *(const float4*)(src + i*4);
    }

    float c = 0.f;

    for (int it = 0; it < TT; it++) {
        int tstep = dir ? (TT - 1 - it) : it;

        /* stage h_{t-1} (32x512) */
        {
            int b  = t >> 3;
            int k0 = (t & 7) * 64;
            float* dst = h_s + b*HS_STRIDE + k0;
            if (it == 0) {
#pragma unroll
                for (int i = 0; i < 16; i++)
                    *(float4*)(dst + i*4) = make_float4(0.f, 0.f, 0.f, 0.f);
            } else {
                const float* src = hbuf + ((it & 1) ? BB*HH : 0) + b*HH + k0;
#pragma unroll
                for (int i = 0; i < 16; i++)
                    *(float4*)(dst + i*4) = __ldcg((const float4*)(src + i*4));
            }
        }
        /* stage xw tile: 32 batch x (4 gates x 8 h) */
        {
            int b = t >> 3, gq = t & 7;
            int gg = gq >> 1, half = (gq & 1) * 4;
            float4 v = *(const float4*)(xw + (size_t)(tstep*32 + b)*G4 + gg*HH + hb + half);
            *(float4*)(xw_s + b*XW_STRIDE + gg*8 + half) = v;
        }
        __syncthreads();

        float a0 = xw_s[lane*XW_STRIDE + 0*8 + w];
        float a1 = xw_s[lane*XW_STRIDE + 1*8 + w];
        float a2 = xw_s[lane*XW_STRIDE + 2*8 + w];
        float a3 = xw_s[lane*XW_STRIDE + 3*8 + w];

        const float4* hp  = (const float4*)(h_s + lane*HS_STRIDE);
        const float4* w0p = (const float4*)(W_s + (0*8 + w)*WS_STRIDE);
        const float4* w1p = (const float4*)(W_s + (1*8 + w)*WS_STRIDE);
        const float4* w2p = (const float4*)(W_s + (2*8 + w)*WS_STRIDE);
        const float4* w3p = (const float4*)(W_s + (3*8 + w)*WS_STRIDE);

#pragma unroll 8
        for (int kk = 0; kk < 128; kk++) {
            float4 hv = hp[kk];
            float4 w0 = w0p[kk], w1 = w1p[kk], w2 = w2p[kk], w3 = w3p[kk];
            a0 = fmaf(hv.x,w0.x, fmaf(hv.y,w0.y, fmaf(hv.z,w0.z, fmaf(hv.w,w0.w, a0))));
            a1 = fmaf(hv.x,w1.x, fmaf(hv.y,w1.y, fmaf(hv.z,w1.z, fmaf(hv.w,w1.w, a1))));
            a2 = fmaf(hv.x,w2.x, fmaf(hv.y,w2.y, fmaf(hv.z,w2.z, fmaf(hv.w,w2.w, a2))));
            a3 = fmaf(hv.x,w3.x, fmaf(hv.y,w3.y, fmaf(hv.z,w3.z, fmaf(hv.w,w3.w, a3))));
        }

        /* torch gate order i, f, g, o */
        float ig = 1.f / (1.f + expf(-a0));
        float fg = 1.f / (1.f + expf(-a1));
        float gg = tanhf(a2);
        float og = 1.f / (1.f + expf(-a3));
        c = fg*c + ig*gg;
        float hv = og * tanhf(c);
        hout_s[w*33 + lane] = hv;
        __syncthreads();

        {
            int b = t >> 3, j = t & 7;
            float v = hout_s[j*33 + b];
            __stcg(hbuf + (((it + 1) & 1) ? BB*HH : 0) + b*HH + hb + j, v);
            if (layer == 0)
                g_l0h[(size_t)(tstep*32 + b)*(2*HH) + dir*HH + hb + j] = __float2bfloat16(v);
            else
                g_l1out[(size_t)(tstep*32 + b)*(2*HH) + dir*HH + hb + j] = v;
        }
        __threadfence();
        dir_sync(dir);
    }
}

/* --------------------- classifier + log_softmax + transpose ---------------- */
__global__ __launch_bounds__(256) void cls_kernel(const float* __restrict__ truth,
        const int* __restrict__ tf, const float* __restrict__ Wc,
        const float* __restrict__ bc, float* __restrict__ out) {
    __shared__ float Fs[64*68];
    __shared__ float Ws[32*68];
    __shared__ float Ls[64*33];
    __shared__ float lse[64];

    int t  = threadIdx.x;
    int p0 = blockIdx.x * 64;
    int p  = t & 63, cg = t >> 6;

    float acc[8];
#pragma unroll
    for (int j = 0; j < 8; j++) acc[j] = 0.f;

    for (int kc = 0; kc < 2*HH; kc += 64) {
        __syncthreads();
#pragma unroll
        for (int pass = 0; pass < 4; pass++) {
            int pp = pass*16 + (t >> 4);
            int kq = (t & 15) * 4;
            *(float4*)(Fs + pp*68 + kq) =
                *(const float4*)(g_l1out + (size_t)(p0 + pp)*(2*HH) + kc + kq);
        }
        {
            int cc = t >> 3, j0 = (t & 7) * 8;
            const float* src = Wc + (size_t)cc*(2*HH + 1) + 1 + kc + j0;
            float* dst = Ws + cc*68 + j0;
#pragma unroll
            for (int i = 0; i < 8; i++) dst[i] = src[i];
        }
        __syncthreads();
#pragma unroll
        for (int kk = 0; kk < 16; kk++) {
            float4 f = *(const float4*)(Fs + p*68 + kk*4);
#pragma unroll
            for (int j = 0; j < 8; j++) {
                float4 wv = *(const float4*)(Ws + (cg*8 + j)*68 + kk*4);
                acc[j] = fmaf(f.x,wv.x, fmaf(f.y,wv.y, fmaf(f.z,wv.z, fmaf(f.w,wv.w, acc[j]))));
            }
        }
    }

    int mp = p0 + p;
    int b  = mp & 31;
    int tt = mp >> 5;
    float past = 0.f;
    if (tt > 0 && tf[0] != 0) past = truth[b*TT + tt - 1];
#pragma unroll
    for (int j = 0; j < 8; j++) {
        int cc = cg*8 + j;
        acc[j] += bc[cc] + past * Wc[(size_t)cc*(2*HH + 1)];
        Ls[p*33 + cc] = acc[j];
    }
    __syncthreads();
    if (t < 64) {
        float m = -1e30f;
#pragma unroll
        for (int cc = 0; cc < CC; cc++) m = fmaxf(m, Ls[t*33 + cc]);
        float s = 0.f;
#pragma unroll
        for (int cc = 0; cc < CC; cc++) s += expf(Ls[t*33 + cc] - m);
        lse[t] = m + logf(s);
    }
    __syncthreads();
    {
        float l = lse[p];
#pragma unroll
        for (int j = 0; j < 8; j++) {
            int cc = cg*8 + j;
            out[(size_t)b*CC*TT + (size_t)cc*TT + tt] = Ls[p*33 + cc] - l;
        }
    }
}

/* ------------------------------- launch ------------------------------------ */
extern "C" void kernel_launch(void* const* d_in, const int* in_sizes, int n_in,
                              void* d_out, int out_size) {
    (void)in_sizes; (void)n_in; (void)out_size;
    const int*   x     = (const int*)  d_in[0];
    const float* truth = (const float*)d_in[1];
    const int*   tf    = (const int*)  d_in[2];
    const float* emb   = (const float*)d_in[3];
    const float* Wih0f = (const float*)d_in[4];
    const float* Whh0f = (const float*)d_in[5];
    const float* bih0f = (const float*)d_in[6];
    const float* bhh0f = (const float*)d_in[7];
    const float* Wih0b = (const float*)d_in[8];
    const float* Whh0b = (const float*)d_in[9];
    const float* bih0b = (const float*)d_in[10];
    const float* bhh0b = (const float*)d_in[11];
    const float* Wih1f = (const float*)d_in[12];
    const float* Whh1f = (const float*)d_in[13];
    const float* bih1f = (const float*)d_in[14];
    const float* bhh1f = (const float*)d_in[15];
    const float* Wih1b = (const float*)d_in[16];
    const float* Whh1b = (const float*)d_in[17];
    const float* bih1b = (const float*)d_in[18];
    const float* bhh1b = (const float*)d_in[19];
    const float* Wc    = (const float*)d_in[20];
    const float* bc    = (const float*)d_in[21];
    float* out = (float*)d_out;

    cudaFuncSetAttribute(lstm_kernel,
                         cudaFuncAttributeMaxDynamicSharedMemorySize, LSTM_SMEM);

    /* resolve device scratch symbol for weight conversion destinations */
    __nv_bfloat16* wbf = nullptr;
    cudaGetSymbolAddress((void**)&wbf, g_Wbf);

    embed_kernel<<<MM/8, 256>>>(x, emb);

    /* convert the 4 Wih matrices to bf16 */
    {
        int n0 = G4*EE  / 4;   /* layer0: 2048*512  */
        int n1 = G4*2*HH / 4;  /* layer1: 2048*1024 */
        f2bf_kernel<<<(n0+255)/256, 256>>>(Wih0f, wbf + WOFF_L0F, n0);
        f2bf_kernel<<<(n0+255)/256, 256>>>(Wih0b, wbf + WOFF_L0B, n0);
        f2bf_kernel<<<(n1+255)/256, 256>>>(Wih1f, wbf + WOFF_L1F, n1);
        f2bf_kernel<<<(n1+255)/256, 256>>>(Wih1b, wbf + WOFF_L1B, n1);
    }

    dim3 g0(G4/GBN, MM/GBM, 2);   /* 16 x 128 x 2 */
    gemm_bf16_kernel<<<g0, 256>>>(0, bih0f, bhh0f, bih0b, bhh0b);
    lstm_kernel<<<NBLK, 256, LSTM_SMEM>>>(0, Whh0f, Whh0b);

    gemm_bf16_kernel<<<g0, 256>>>(1, bih1f, bhh1f, bih1b, bhh1b);
    lstm_kernel<<<NBLK, 256, LSTM_SMEM>>>(1, Whh1f, Whh1b);

    cls_kernel<<<MM/64, 256>>>(truth, tf, Wc, bc, out);
}

// round 6
// speedup vs baseline: 2.4730x; 2.1625x over previous
#include <cuda_runtime.h>
#include <cuda_bf16.h>
#include <math.h>
#include <stdint.h>

#define BB 32
#define TT 512
#define EE 512
#define HH 512
#define CC 32
#define MM (BB*TT)        /* 16384 token positions, m' = t*32 + b */
#define G4 (4*HH)         /* 2048 gate columns per direction */
#define NBLK 128          /* persistent LSTM grid: 64 blocks per direction */

/* ------------------------ scratch (static device memory) ------------------- */
__device__ __nv_bfloat16 g_embh[(size_t)MM*EE];    /* layer0 GEMM input (bf16) */
__device__ __nv_bfloat16 g_l0h[(size_t)MM*2*HH];   /* layer0 output     (bf16) */
__device__ __nv_bfloat16 g_Wbf[2*(size_t)G4*EE + 2*(size_t)G4*2*HH]; /* Wih bf16 */
__device__ __nv_bfloat16 g_Whbf[4*(size_t)G4*HH];  /* Whh bf16 (4 matrices)    */
__device__ float g_xw0[(size_t)MM*G4];             /* xw forward  [m'][2048]   */
__device__ float g_xw1[(size_t)MM*G4];             /* xw backward [m'][2048]   */
__device__ float g_l1out[(size_t)MM*2*HH];         /* layer1 output [m'][1024] */
__device__ __nv_bfloat16 g_hbuf_bf[2*2*BB*HH];     /* [dir][parity][b][h] bf16 */
__device__ unsigned g_bar_cnt[2] = {0, 0};
__device__ unsigned g_bar_gen[2] = {0, 0};

/* Wbf offsets (Wih) */
#define WOFF_L0F ((size_t)0)
#define WOFF_L0B ((size_t)G4*EE)
#define WOFF_L1F ((size_t)2*G4*EE)
#define WOFF_L1B ((size_t)2*G4*EE + (size_t)G4*2*HH)
/* Whbf offsets (Whh) */
#define WH_L0F ((size_t)0)
#define WH_L0B ((size_t)G4*HH)
#define WH_L1F ((size_t)2*G4*HH)
#define WH_L1B ((size_t)3*G4*HH)

/* --------------------- per-direction grid barrier (64 blocks) -------------- */
__device__ __forceinline__ void dir_sync(int dir) {
    __syncthreads();
    if (threadIdx.x == 0) {
        unsigned gen = *(volatile unsigned*)&g_bar_gen[dir];
        __threadfence();
        if (atomicAdd(&g_bar_cnt[dir], 1u) == (NBLK/2) - 1) {
            atomicExch(&g_bar_cnt[dir], 0u);
            __threadfence();
            atomicAdd(&g_bar_gen[dir], 1u);
        } else {
            while (*(volatile unsigned*)&g_bar_gen[dir] == gen) { }
        }
        __threadfence();
    }
    __syncthreads();
}

/* ------------------------------ embedding (f32 -> bf16) -------------------- */
__global__ __launch_bounds__(256) void embed_kernel(const int* __restrict__ x,
                                                    const float* __restrict__ emb) {
    int gid  = blockIdx.x * blockDim.x + threadIdx.x;
    int mp   = gid >> 5;
    int lane = gid & 31;
    int b  = mp & 31;
    int tt = mp >> 5;
    int v  = x[b*TT + tt];
    const float4* src = (const float4*)(emb + (size_t)v*EE);
    __nv_bfloat162* dst = (__nv_bfloat162*)(g_embh + (size_t)mp*EE);
#pragma unroll
    for (int r = 0; r < EE/128; r++) {
        float4 f = src[r*32 + lane];
        dst[(r*32 + lane)*2 + 0] = __floats2bfloat162_rn(f.x, f.y);
        dst[(r*32 + lane)*2 + 1] = __floats2bfloat162_rn(f.z, f.w);
    }
}

/* --------------------------- f32 -> bf16 convert --------------------------- */
__global__ __launch_bounds__(256) void f2bf_kernel(const float* __restrict__ src,
                                                   __nv_bfloat16* __restrict__ dst,
                                                   int n4) {
    int i = blockIdx.x * blockDim.x + threadIdx.x;
    if (i < n4) {
        float4 f = *(const float4*)(src + (size_t)i*4);
        __nv_bfloat162* d = (__nv_bfloat162*)(dst + (size_t)i*4);
        d[0] = __floats2bfloat162_rn(f.x, f.y);
        d[1] = __floats2bfloat162_rn(f.z, f.w);
    }
}

/* ----------------------------- mma helpers --------------------------------- */
__device__ __forceinline__ void ldmatrix_x4(uint32_t& d0, uint32_t& d1,
                                            uint32_t& d2, uint32_t& d3,
                                            uint32_t addr) {
    asm volatile("ldmatrix.sync.aligned.m8n8.x4.shared.b16 {%0,%1,%2,%3}, [%4];"
                 : "=r"(d0), "=r"(d1), "=r"(d2), "=r"(d3) : "r"(addr));
}
__device__ __forceinline__ void mma_bf16(float* c, const uint32_t* a, const uint32_t* b) {
    asm volatile("mma.sync.aligned.m16n8k16.row.col.f32.bf16.bf16.f32 "
                 "{%0,%1,%2,%3}, {%4,%5,%6,%7}, {%8,%9}, {%0,%1,%2,%3};"
                 : "+f"(c[0]), "+f"(c[1]), "+f"(c[2]), "+f"(c[3])
                 : "r"(a[0]), "r"(a[1]), "r"(a[2]), "r"(a[3]), "r"(b[0]), "r"(b[1]));
}

/* ---------------- bf16 tensor-core GEMM: xw = A @ W^T + bih + bhh ---------- */
#define GBM 128
#define GBN 128
#define GBK 32
#define LDS_W 40

__global__ __launch_bounds__(256) void gemm_bf16_kernel(
        int layer,
        const float* __restrict__ bif, const float* __restrict__ bhf,
        const float* __restrict__ bib, const float* __restrict__ bhb) {
    const int K = layer ? 2*HH : EE;
    const __nv_bfloat16* A = layer ? g_l0h : g_embh;
    int dir = blockIdx.z;
    const __nv_bfloat16* W = g_Wbf + (layer ? (dir ? WOFF_L1B : WOFF_L1F)
                                            : (dir ? WOFF_L0B : WOFF_L0F));
    const float* bi = dir ? bib : bif;
    const float* bh = dir ? bhb : bhf;
    float* out = dir ? g_xw1 : g_xw0;

    __shared__ __nv_bfloat16 As[GBM*LDS_W];
    __shared__ __nv_bfloat16 Bs[GBN*LDS_W];

    int t = threadIdx.x;
    int m0 = blockIdx.y * GBM;
    int n0 = blockIdx.x * GBN;
    int warp = t >> 5, lane = t & 31;
    int wm0 = (warp & 3) * 32;
    int wn0 = (warp >> 2) * 64;

    int lr = t >> 2;
    int lc = (t & 3) * 8;
    const __nv_bfloat16* Ag = A + (size_t)(m0 + lr) * K + lc;
    const __nv_bfloat16* Wg = W + (size_t)(n0 + lr) * K + lc;

    float c[2][8][4];
#pragma unroll
    for (int i = 0; i < 2; i++)
#pragma unroll
        for (int j = 0; j < 8; j++)
#pragma unroll
            for (int q = 0; q < 4; q++) c[i][j][q] = 0.f;

    int arow = (lane & 7) + ((lane >> 3) & 1) * 8;
    int acol = (lane >> 4) * 8;
    int brow = ((lane >> 4) * 8) + (lane & 7);
    int bcol = ((lane >> 3) & 1) * 8;

    uint32_t as_base = (uint32_t)__cvta_generic_to_shared(As);
    uint32_t bs_base = (uint32_t)__cvta_generic_to_shared(Bs);

    const int nk = K / GBK;
    uint4 pa0 = *(const uint4*)(Ag);
    uint4 pa1 = *(const uint4*)(Ag + (size_t)64*K);
    uint4 pb0 = *(const uint4*)(Wg);
    uint4 pb1 = *(const uint4*)(Wg + (size_t)64*K);

    for (int kt = 0; kt < nk; kt++) {
        *(uint4*)(As + lr*LDS_W + lc)        = pa0;
        *(uint4*)(As + (lr+64)*LDS_W + lc)   = pa1;
        *(uint4*)(Bs + lr*LDS_W + lc)        = pb0;
        *(uint4*)(Bs + (lr+64)*LDS_W + lc)   = pb1;
        __syncthreads();
        if (kt + 1 < nk) {
            int ko = (kt + 1) * GBK;
            pa0 = *(const uint4*)(Ag + ko);
            pa1 = *(const uint4*)(Ag + (size_t)64*K + ko);
            pb0 = *(const uint4*)(Wg + ko);
            pb1 = *(const uint4*)(Wg + (size_t)64*K + ko);
        }
#pragma unroll
        for (int ks = 0; ks < GBK; ks += 16) {
            uint32_t a[2][4];
            uint32_t b[8][2];
#pragma unroll
            for (int mt = 0; mt < 2; mt++) {
                uint32_t addr = as_base +
                    (uint32_t)(((wm0 + mt*16 + arow)*LDS_W + ks + acol) * 2);
                ldmatrix_x4(a[mt][0], a[mt][1], a[mt][2], a[mt][3], addr);
            }
#pragma unroll
            for (int p = 0; p < 4; p++) {
                uint32_t addr = bs_base +
                    (uint32_t)(((wn0 + p*16 + brow)*LDS_W + ks + bcol) * 2);
                ldmatrix_x4(b[2*p][0], b[2*p][1], b[2*p+1][0], b[2*p+1][1], addr);
            }
#pragma unroll
            for (int mt = 0; mt < 2; mt++)
#pragma unroll
                for (int nt = 0; nt < 8; nt++)
                    mma_bf16(c[mt][nt], a[mt], b[nt]);
        }
        __syncthreads();
    }

    int g  = lane >> 2;
    int cp = (lane & 3) * 2;
#pragma unroll
    for (int nt = 0; nt < 8; nt++) {
        int n = n0 + wn0 + nt*8 + cp;
        float b0 = bi[n]   + bh[n];
        float b1 = bi[n+1] + bh[n+1];
#pragma unroll
        for (int mt = 0; mt < 2; mt++) {
            int r = m0 + wm0 + mt*16 + g;
            float2 v0 = make_float2(c[mt][nt][0] + b0, c[mt][nt][1] + b1);
            float2 v1 = make_float2(c[mt][nt][2] + b0, c[mt][nt][3] + b1);
            *(float2*)(out + (size_t)r*G4 + n)       = v0;
            *(float2*)(out + (size_t)(r+8)*G4 + n)   = v1;
        }
    }
}

/* ------------------- persistent recurrent scan (bf16 MMA) ------------------ */
#define LW 520                       /* bf16 row stride: 1040B, %128 = 16 -> LDSM conflict-free */
#define GST 34                       /* gate smem row stride (floats) */
#define LSTM_SMEM (32*LW*2*2 + 2*32*GST*4)

__global__ __launch_bounds__(256) void lstm_mma_kernel(int layer) {
    extern __shared__ __align__(16) char smraw[];
    __nv_bfloat16* h_s = (__nv_bfloat16*)smraw;   /* [32][LW] h_{t-1}  */
    __nv_bfloat16* W_s = h_s + 32*LW;             /* [32][LW] Whh slice */
    float* G_s = (float*)(W_s + 32*LW);           /* [2][32][GST] gate partials */

    int t = threadIdx.x;
    int warp = t >> 5, lane = t & 31;
    int dir = blockIdx.x >> 6;
    int hb  = (blockIdx.x & 63) << 3;
    const __nv_bfloat16* Whh = g_Whbf + (layer ? (dir ? WH_L1B : WH_L1F)
                                               : (dir ? WH_L0B : WH_L0F));
    const float* xw = dir ? g_xw1 : g_xw0;
    __nv_bfloat16* hbuf = g_hbuf_bf + dir*2*BB*HH;

    /* stage Whh slice once: W_s[g*8+j][k] <- Whh[g*512 + hb + j][k] */
    {
        int r  = t >> 3;              /* 0..31 */
        int g  = r >> 3, j = r & 7;
        int kq = (t & 7) * 64;
        const uint4* src = (const uint4*)(Whh + (size_t)(g*HH + hb + j)*HH + kq);
        uint4* dst = (uint4*)(W_s + r*LW + kq);
#pragma unroll
        for (int i = 0; i < 8; i++) dst[i] = src[i];
    }

    /* warp tile: 2(M16) x 2(N16) x 2(K256) */
    int mb = (warp & 1) * 16;
    int nb = ((warp >> 1) & 1) * 16;
    int kb = (warp >> 2) * 256;
    float* Gk = G_s + (warp >> 2) * 32 * GST;

    int arow = (lane & 7) + ((lane >> 3) & 1) * 8;
    int acol = (lane >> 4) * 8;
    int brow = ((lane >> 4) * 8) + (lane & 7);
    int bcol = ((lane >> 3) & 1) * 8;
    uint32_t hs_base = (uint32_t)__cvta_generic_to_shared(h_s);
    uint32_t ws_base = (uint32_t)__cvta_generic_to_shared(W_s);

    /* gate-math mapping: thread -> (batch gb, local hcol gj) */
    int gb = t >> 3;
    int gj = t & 7;

    float c = 0.f;

    for (int it = 0; it < TT; it++) {
        int tstep = dir ? (TT - 1 - it) : it;

        /* prefetch xw for this thread's gate math (independent of h) */
        const float* xp = xw + (size_t)(tstep*32 + gb)*G4 + hb + gj;
        float x0 = __ldg(xp + 0*HH);
        float x1 = __ldg(xp + 1*HH);
        float x2 = __ldg(xp + 2*HH);
        float x3 = __ldg(xp + 3*HH);

        /* stage h_{t-1} (32x512 bf16 = 32KB) */
        {
            int r  = t >> 3;
            int kq = (t & 7) * 64;
            uint4* dst = (uint4*)(h_s + r*LW + kq);
            if (it == 0) {
                uint4 z = make_uint4(0u,0u,0u,0u);
#pragma unroll
                for (int i = 0; i < 8; i++) dst[i] = z;
            } else {
                const uint4* src = (const uint4*)(hbuf + ((it & 1) ? BB*HH : 0) + r*HH + kq);
#pragma unroll
                for (int i = 0; i < 8; i++) dst[i] = __ldcg(src + i);
            }
        }
        __syncthreads();

        float acc[2][4];
#pragma unroll
        for (int nt = 0; nt < 2; nt++)
#pragma unroll
            for (int q = 0; q < 4; q++) acc[nt][q] = 0.f;

#pragma unroll
        for (int ks = 0; ks < 16; ks++) {
            uint32_t a[4], b0[2], b1[2];
            uint32_t addrA = hs_base + (uint32_t)(((mb + arow)*LW + kb + ks*16 + acol) * 2);
            ldmatrix_x4(a[0], a[1], a[2], a[3], addrA);
            uint32_t addrB = ws_base + (uint32_t)(((nb + brow)*LW + kb + ks*16 + bcol) * 2);
            ldmatrix_x4(b0[0], b0[1], b1[0], b1[1], addrB);
            mma_bf16(acc[0], a, b0);
            mma_bf16(acc[1], a, b1);
        }

        /* C fragments -> gate smem (K-split partials) */
        {
            int g  = lane >> 2;
            int cp = (lane & 3) * 2;
#pragma unroll
            for (int nt = 0; nt < 2; nt++) {
                *(float2*)(Gk + (mb + g)*GST     + nb + nt*8 + cp) = make_float2(acc[nt][0], acc[nt][1]);
                *(float2*)(Gk + (mb + g + 8)*GST + nb + nt*8 + cp) = make_float2(acc[nt][2], acc[nt][3]);
            }
        }
        __syncthreads();

        /* gate math: thread (gb, gj); gate rows g*8+gj in the 32-row slice */
        {
            float a0 = x0 + G_s[gb*GST + 0*8 + gj] + G_s[32*GST + gb*GST + 0*8 + gj];
            float a1 = x1 + G_s[gb*GST + 1*8 + gj] + G_s[32*GST + gb*GST + 1*8 + gj];
            float a2 = x2 + G_s[gb*GST + 2*8 + gj] + G_s[32*GST + gb*GST + 2*8 + gj];
            float a3 = x3 + G_s[gb*GST + 3*8 + gj] + G_s[32*GST + gb*GST + 3*8 + gj];
            float ig = 1.f / (1.f + expf(-a0));
            float fg = 1.f / (1.f + expf(-a1));
            float gg = tanhf(a2);
            float og = 1.f / (1.f + expf(-a3));
            c = fg*c + ig*gg;
            float hv = og * tanhf(c);
            __nv_bfloat16 hbv = __float2bfloat16(hv);
            hbuf[(((it + 1) & 1) ? BB*HH : 0) + gb*HH + hb + gj] = hbv;
            if (layer == 0)
                g_l0h[(size_t)(tstep*32 + gb)*(2*HH) + dir*HH + hb + gj] = hbv;
            else
                g_l1out[(size_t)(tstep*32 + gb)*(2*HH) + dir*HH + hb + gj] = hv;
        }
        __threadfence();
        dir_sync(dir);
    }
}

/* --------------------- classifier + log_softmax + transpose ---------------- */
__global__ __launch_bounds__(256) void cls_kernel(const float* __restrict__ truth,
        const int* __restrict__ tf, const float* __restrict__ Wc,
        const float* __restrict__ bc, float* __restrict__ out) {
    __shared__ float Fs[64*68];
    __shared__ float Ws[32*68];
    __shared__ float Ls[64*33];
    __shared__ float lse[64];

    int t  = threadIdx.x;
    int p0 = blockIdx.x * 64;
    int p  = t & 63, cg = t >> 6;

    float acc[8];
#pragma unroll
    for (int j = 0; j < 8; j++) acc[j] = 0.f;

    for (int kc = 0; kc < 2*HH; kc += 64) {
        __syncthreads();
#pragma unroll
        for (int pass = 0; pass < 4; pass++) {
            int pp = pass*16 + (t >> 4);
            int kq = (t & 15) * 4;
            *(float4*)(Fs + pp*68 + kq) =
                *(const float4*)(g_l1out + (size_t)(p0 + pp)*(2*HH) + kc + kq);
        }
        {
            int cc = t >> 3, j0 = (t & 7) * 8;
            const float* src = Wc + (size_t)cc*(2*HH + 1) + 1 + kc + j0;
            float* dst = Ws + cc*68 + j0;
#pragma unroll
            for (int i = 0; i < 8; i++) dst[i] = src[i];
        }
        __syncthreads();
#pragma unroll
        for (int kk = 0; kk < 16; kk++) {
            float4 f = *(const float4*)(Fs + p*68 + kk*4);
#pragma unroll
            for (int j = 0; j < 8; j++) {
                float4 wv = *(const float4*)(Ws + (cg*8 + j)*68 + kk*4);
                acc[j] = fmaf(f.x,wv.x, fmaf(f.y,wv.y, fmaf(f.z,wv.z, fmaf(f.w,wv.w, acc[j]))));
            }
        }
    }

    int mp = p0 + p;
    int b  = mp & 31;
    int tt = mp >> 5;
    float past = 0.f;
    if (tt > 0 && tf[0] != 0) past = truth[b*TT + tt - 1];
#pragma unroll
    for (int j = 0; j < 8; j++) {
        int cc = cg*8 + j;
        acc[j] += bc[cc] + past * Wc[(size_t)cc*(2*HH + 1)];
        Ls[p*33 + cc] = acc[j];
    }
    __syncthreads();
    if (t < 64) {
        float m = -1e30f;
#pragma unroll
        for (int cc = 0; cc < CC; cc++) m = fmaxf(m, Ls[t*33 + cc]);
        float s = 0.f;
#pragma unroll
        for (int cc = 0; cc < CC; cc++) s += expf(Ls[t*33 + cc] - m);
        lse[t] = m + logf(s);
    }
    __syncthreads();
    {
        float l = lse[p];
#pragma unroll
        for (int j = 0; j < 8; j++) {
            int cc = cg*8 + j;
            out[(size_t)b*CC*TT + (size_t)cc*TT + tt] = Ls[p*33 + cc] - l;
        }
    }
}

/* ------------------------------- launch ------------------------------------ */
extern "C" void kernel_launch(void* const* d_in, const int* in_sizes, int n_in,
                              void* d_out, int out_size) {
    (void)in_sizes; (void)n_in; (void)out_size;
    const int*   x     = (const int*)  d_in[0];
    const float* truth = (const float*)d_in[1];
    const int*   tf    = (const int*)  d_in[2];
    const float* emb   = (const float*)d_in[3];
    const float* Wih0f = (const float*)d_in[4];
    const float* Whh0f = (const float*)d_in[5];
    const float* bih0f = (const float*)d_in[6];
    const float* bhh0f = (const float*)d_in[7];
    const float* Wih0b = (const float*)d_in[8];
    const float* Whh0b = (const float*)d_in[9];
    const float* bih0b = (const float*)d_in[10];
    const float* bhh0b = (const float*)d_in[11];
    const float* Wih1f = (const float*)d_in[12];
    const float* Whh1f = (const float*)d_in[13];
    const float* bih1f = (const float*)d_in[14];
    const float* bhh1f = (const float*)d_in[15];
    const float* Wih1b = (const float*)d_in[16];
    const float* Whh1b = (const float*)d_in[17];
    const float* bih1b = (const float*)d_in[18];
    const float* bhh1b = (const float*)d_in[19];
    const float* Wc    = (const float*)d_in[20];
    const float* bc    = (const float*)d_in[21];
    float* out = (float*)d_out;

    cudaFuncSetAttribute(lstm_mma_kernel,
                         cudaFuncAttributeMaxDynamicSharedMemorySize, LSTM_SMEM);

    __nv_bfloat16* wbf = nullptr;
    cudaGetSymbolAddress((void**)&wbf, g_Wbf);
    __nv_bfloat16* whbf = nullptr;
    cudaGetSymbolAddress((void**)&whbf, g_Whbf);

    embed_kernel<<<MM/8, 256>>>(x, emb);

    /* convert Wih + Whh matrices to bf16 */
    {
        int n0 = G4*EE  / 4;   /* 2048*512/4  */
        int n1 = G4*2*HH / 4;  /* 2048*1024/4 */
        int nh = G4*HH  / 4;   /* 2048*512/4  */
        f2bf_kernel<<<(n0+255)/256, 256>>>(Wih0f, wbf + WOFF_L0F, n0);
        f2bf_kernel<<<(n0+255)/256, 256>>>(Wih0b, wbf + WOFF_L0B, n0);
        f2bf_kernel<<<(n1+255)/256, 256>>>(Wih1f, wbf + WOFF_L1F, n1);
        f2bf_kernel<<<(n1+255)/256, 256>>>(Wih1b, wbf + WOFF_L1B, n1);
        f2bf_kernel<<<(nh+255)/256, 256>>>(Whh0f, whbf + WH_L0F, nh);
        f2bf_kernel<<<(nh+255)/256, 256>>>(Whh0b, whbf + WH_L0B, nh);
        f2bf_kernel<<<(nh+255)/256, 256>>>(Whh1f, whbf + WH_L1F, nh);
        f2bf_kernel<<<(nh+255)/256, 256>>>(Whh1b, whbf + WH_L1B, nh);
    }

    dim3 g0(G4/GBN, MM/GBM, 2);   /* 16 x 128 x 2 */
    gemm_bf16_kernel<<<g0, 256>>>(0, bih0f, bhh0f, bih0b, bhh0b);
    lstm_mma_kernel<<<NBLK, 256, LSTM_SMEM>>>(0);

    gemm_bf16_kernel<<<g0, 256>>>(1, bih1f, bhh1f, bih1b, bhh1b);
    lstm_mma_kernel<<<NBLK, 256, LSTM_SMEM>>>(1);

    cls_kernel<<<MM/64, 256>>>(truth, tf, Wc, bc, out);
}